// round 4
// baseline (speedup 1.0000x reference)
#include <cuda_runtime.h>
#include <math.h>

#define NN   50000
#define DH   128
#define DOUT 57
#define TOTE (800000 + NN)

// -------- scratch (__device__ globals; no allocation allowed) --------
__device__ float4 g_h4[NN * 32];   // GEMM output h (both layers)  [N,128]
__device__ float4 g_t4[NN * 32];   // aggregation output            [N,128]
__device__ float  g_as[NN];        // alpha_src per node
__device__ float  g_ad[NN];        // alpha_dst per node
__device__ int    g_deg[NN];
__device__ int    g_off[NN + 1];
__device__ int    g_cur[NN];
__device__ int    g_srcs[TOTE];    // CSR (by dst): src node per edge

// ---------------- f32x2 packed-FMA helpers (sm_103a) ----------------
__device__ __forceinline__ unsigned long long pack2(float v) {
    unsigned long long r;
    asm("mov.b64 %0, {%1, %1};" : "=l"(r) : "f"(v));
    return r;
}
__device__ __forceinline__ void fma2(unsigned long long& d,
                                     unsigned long long a, unsigned long long b) {
    asm("fma.rn.f32x2 %0, %1, %2, %0;" : "+l"(d) : "l"(a), "l"(b));
}
__device__ __forceinline__ float2 unpack2(unsigned long long v) {
    float x, y;
    asm("mov.b64 {%0, %1}, %2;" : "=f"(x), "=f"(y) : "l"(v));
    return make_float2(x, y);
}

// ============================ CSR build ============================
__global__ void k_init_deg() {
    int n = blockIdx.x * blockDim.x + threadIdx.x;
    if (n < NN) g_deg[n] = 1;      // +1 = self loop
}

// dst row, 4 edges per thread
__global__ void k_count(const int* __restrict__ ei, int E) {
    int e4 = blockIdx.x * blockDim.x + threadIdx.x;
    if (e4 * 4 < E) {
        int4 d = ((const int4*)(ei + E))[e4];
        if (d.x >= 0 && d.x < NN) atomicAdd(&g_deg[d.x], 1);
        if (d.y >= 0 && d.y < NN) atomicAdd(&g_deg[d.y], 1);
        if (d.z >= 0 && d.z < NN) atomicAdd(&g_deg[d.z], 1);
        if (d.w >= 0 && d.w < NN) atomicAdd(&g_deg[d.w], 1);
    }
}

// single-block exclusive scan of g_deg -> g_off, then self-loops + g_cur init
__global__ void k_scan() {
    __shared__ int sums[1024];
    const int n = NN;
    int tid = threadIdx.x;
    const int chunk = (n + 1023) / 1024;
    int base = tid * chunk;
    int s = 0;
    for (int i = 0; i < chunk; ++i) {
        int idx = base + i;
        if (idx < n) s += g_deg[idx];
    }
    sums[tid] = s;
    __syncthreads();
    for (int d = 1; d < 1024; d <<= 1) {
        int v = (tid >= d) ? sums[tid - d] : 0;
        __syncthreads();
        sums[tid] += v;
        __syncthreads();
    }
    int run = (tid == 0) ? 0 : sums[tid - 1];
    for (int i = 0; i < chunk; ++i) {
        int idx = base + i;
        if (idx < n) { g_off[idx] = run; run += g_deg[idx]; }
    }
    if (tid == 1023) g_off[n] = sums[1023];
    __syncthreads();
    // self loops in slot 0 of each segment + scatter cursor
    for (int m = tid; m < n; m += 1024) {
        int p = g_off[m];
        g_srcs[p] = m;
        g_cur[m] = p + 1;
    }
}

__global__ void k_scatter(const int* __restrict__ ei, int E) {
    int e4 = blockIdx.x * blockDim.x + threadIdx.x;
    if (e4 * 4 < E) {
        int4 sv = ((const int4*)ei)[e4];
        int4 dv = ((const int4*)(ei + E))[e4];
        int ss[4] = {sv.x, sv.y, sv.z, sv.w};
        int dd[4] = {dv.x, dv.y, dv.z, dv.w};
#pragma unroll
        for (int k = 0; k < 4; ++k) {
            int d = dd[k], s = ss[k];
            if (d >= 0 && d < NN && s >= 0 && s < NN) {
                int p = atomicAdd(&g_cur[d], 1);
                if (p >= 0 && p < TOTE) g_srcs[p] = s;
            }
        }
    }
}

// ============================ GEMM (fused alpha, f32x2) ============================
// C[M,Wn] = act(A)[M,128] @ W[128,Wn]   (M = NN)
// MODE 0: A=ext(x),  C=g_h4, no relu, fused alpha (a1)
// MODE 1: A=g_t4,    C=g_h4, relu-in, fused alpha (a2)
// MODE 2: A=g_t4,    C=ext(d_out), Wn=57, +bias
template <int MODE>
__global__ void gemm_kernel(const float4* __restrict__ Aext,
                            const float* __restrict__ W,
                            const float* __restrict__ avs,
                            const float* __restrict__ avd,
                            const float* __restrict__ bias,
                            float* __restrict__ Cext) {
    constexpr int  Wn   = (MODE == 2) ? DOUT : DH;
    constexpr bool RELU = (MODE == 1);
    // [64 k-rows][128 cols] as ulonglong2 (4 floats each): 64*32*16B = 32 KB
    __shared__ ulonglong2 Ws2[64 * 32];

    const float4* A = (MODE == 0) ? Aext : g_t4;

    int tid = threadIdx.x;                        // 256 threads
    int tx = tid & 31, ty = tid >> 5;
    int rowBase = blockIdx.x * 64 + ty * 8;
    int rmax = NN - rowBase;                      // warp-uniform

    unsigned long long accL[8], accH[8];
#pragma unroll
    for (int i = 0; i < 8; ++i) { accL[i] = 0ull; accH[i] = 0ull; }  // (0.f,0.f)

    float* Wsf = (float*)Ws2;
    for (int half = 0; half < 2; ++half) {
        // stage W rows [half*64, half*64+64), zero-padded to 128 cols
        for (int i = tid; i < 64 * DH; i += 256) {
            int k = i >> 7, c = i & 127;
            Wsf[i] = (c < Wn) ? W[(half * 64 + k) * Wn + c] : 0.f;
        }
        __syncthreads();

#pragma unroll 2
        for (int k4 = 0; k4 < 16; ++k4) {
            ulonglong2 w0 = Ws2[(k4 * 4 + 0) * 32 + tx];
            ulonglong2 w1 = Ws2[(k4 * 4 + 1) * 32 + tx];
            ulonglong2 w2 = Ws2[(k4 * 4 + 2) * 32 + tx];
            ulonglong2 w3 = Ws2[(k4 * 4 + 3) * 32 + tx];
#pragma unroll
            for (int i = 0; i < 8; ++i) {
                if (i < rmax) {
                    float4 a = A[(rowBase + i) * 32 + half * 16 + k4];
                    if (RELU) {
                        a.x = fmaxf(a.x, 0.f); a.y = fmaxf(a.y, 0.f);
                        a.z = fmaxf(a.z, 0.f); a.w = fmaxf(a.w, 0.f);
                    }
                    unsigned long long ax = pack2(a.x), ay = pack2(a.y);
                    unsigned long long az = pack2(a.z), aw = pack2(a.w);
                    fma2(accL[i], ax, w0.x); fma2(accH[i], ax, w0.y);
                    fma2(accL[i], ay, w1.x); fma2(accH[i], ay, w1.y);
                    fma2(accL[i], az, w2.x); fma2(accH[i], az, w2.y);
                    fma2(accL[i], aw, w3.x); fma2(accH[i], aw, w3.y);
                }
            }
        }
        __syncthreads();
    }

    if (MODE < 2) {
        float as0 = avs[4 * tx + 0], as1 = avs[4 * tx + 1], as2 = avs[4 * tx + 2], as3 = avs[4 * tx + 3];
        float ad0 = avd[4 * tx + 0], ad1 = avd[4 * tx + 1], ad2 = avd[4 * tx + 2], ad3 = avd[4 * tx + 3];
#pragma unroll
        for (int i = 0; i < 8; ++i) {
            if (i < rmax) {
                int row = rowBase + i;
                float2 lo = unpack2(accL[i]), hi = unpack2(accH[i]);
                float4 acc = make_float4(lo.x, lo.y, hi.x, hi.y);
                g_h4[row * 32 + tx] = acc;
                float ps = acc.x * as0 + acc.y * as1 + acc.z * as2 + acc.w * as3;
                float pd = acc.x * ad0 + acc.y * ad1 + acc.z * ad2 + acc.w * ad3;
#pragma unroll
                for (int o = 16; o; o >>= 1) {
                    ps += __shfl_xor_sync(0xffffffffu, ps, o);
                    pd += __shfl_xor_sync(0xffffffffu, pd, o);
                }
                if (tx == 0) { g_as[row] = ps; g_ad[row] = pd; }
            }
        }
    } else {
#pragma unroll
        for (int i = 0; i < 8; ++i) {
            if (i < rmax) {
                int row = rowBase + i;
                float2 lo = unpack2(accL[i]), hi = unpack2(accH[i]);
                float v[4] = {lo.x, lo.y, hi.x, hi.y};
#pragma unroll
                for (int j = 0; j < 4; ++j) {
                    int col = 4 * tx + j;
                    if (col < DOUT) Cext[row * DOUT + col] = v[j] + bias[col];
                }
            }
        }
    }
}

// ==================== segment softmax + aggregation ====================
// one warp per destination node; online softmax (merged max+denominator),
// then one weighted-aggregation pass. out = g_t4 = segsum(w * h[src]) + bias
__global__ void agg_kernel(const float* __restrict__ bias) {
    int w = (blockIdx.x * blockDim.x + threadIdx.x) >> 5;
    if (w >= NN) return;
    int lane = threadIdx.x & 31;
    int beg = g_off[w], end = g_off[w + 1];
    float adn = g_ad[w];

    // pass 1: online (max, denominator) in one edge scan
    float m = -1e30f, den = 0.f;            // finite init: avoids 0*exp(nan)
    for (int j = beg + lane; j < end; j += 32) {
        float e = g_as[g_srcs[j]] + adn;
        e = (e > 0.f) ? e : 0.2f * e;
        float mn = fmaxf(m, e);
        den = den * __expf(m - mn) + __expf(e - mn);
        m = mn;
    }
#pragma unroll
    for (int o = 16; o; o >>= 1) {
        float mo = __shfl_xor_sync(0xffffffffu, m, o);
        float do_ = __shfl_xor_sync(0xffffffffu, den, o);
        float mn = fmaxf(m, mo);
        den = den * __expf(m - mn) + do_ * __expf(mo - mn);
        m = mn;
    }
    float inv = 1.0f / den;

    // pass 2: weighted aggregation; lane owns 4 of 128 dims
    float4 acc = make_float4(0.f, 0.f, 0.f, 0.f);
    for (int j = beg; j < end; ++j) {
        int s = g_srcs[j];
        float e = g_as[s] + adn;
        e = (e > 0.f) ? e : 0.2f * e;
        float wgt = __expf(e - m) * inv;
        float4 hv = g_h4[s * 32 + lane];
        acc.x += wgt * hv.x; acc.y += wgt * hv.y;
        acc.z += wgt * hv.z; acc.w += wgt * hv.w;
    }
    float b0 = bias[4 * lane + 0], b1 = bias[4 * lane + 1];
    float b2 = bias[4 * lane + 2], b3 = bias[4 * lane + 3];
    g_t4[w * 32 + lane] = make_float4(acc.x + b0, acc.y + b1, acc.z + b2, acc.w + b3);
}

// ============================ launch ============================
extern "C" void kernel_launch(void* const* d_in, const int* in_sizes, int n_in,
                              void* d_out, int out_size) {
    const float* x   = (const float*)d_in[0];
    const int*   ei  = (const int*)d_in[1];     // int32 (JAX x64-disabled)
    const float* W1  = (const float*)d_in[2];
    const float* a1s = (const float*)d_in[3];
    const float* a1d = (const float*)d_in[4];
    const float* b1  = (const float*)d_in[5];
    const float* W2  = (const float*)d_in[6];
    const float* a2s = (const float*)d_in[7];
    const float* a2d = (const float*)d_in[8];
    const float* b2  = (const float*)d_in[9];
    const float* fcw = (const float*)d_in[10];
    const float* fcb = (const float*)d_in[11];
    float*       out = (float*)d_out;
    int E = in_sizes[1] / 2;
    int E4 = (E + 3) / 4;

    int gemm_blocks = (NN + 63) / 64;
    int agg_blocks  = (NN * 32 + 255) / 256;

    // CSR build (rebuilt every call; deterministic work)
    k_init_deg<<<(NN + 255) / 256, 256>>>();
    k_count<<<(E4 + 255) / 256, 256>>>(ei, E);
    k_scan<<<1, 1024>>>();
    k_scatter<<<(E4 + 255) / 256, 256>>>(ei, E);

    // layer 1
    gemm_kernel<0><<<gemm_blocks, 256>>>((const float4*)x, W1, a1s, a1d, nullptr, nullptr);
    agg_kernel<<<agg_blocks, 256>>>(b1);
    // layer 2 (relu applied to input inside GEMM)
    gemm_kernel<1><<<gemm_blocks, 256>>>(nullptr, W2, a2s, a2d, nullptr, nullptr);
    agg_kernel<<<agg_blocks, 256>>>(b2);
    // output head
    gemm_kernel<2><<<gemm_blocks, 256>>>(nullptr, fcw, nullptr, nullptr, fcb, out);
}